// round 2
// baseline (speedup 1.0000x reference)
#include <cuda_runtime.h>

// GraphConvolution: out[b] = adj[b] @ (x[b] @ W) + bias
// B=8, N=2048, F_IN=F_OUT=128.
// 3xTF32 error-compensated mma.sync GEMM, two phases.
//   For each product: acc += a*b + a_lo*b + a*b_lo   (a_lo = a - trunc19(a), exact)
//   HW truncation of the raw fp32 operand supplies the "hi" term for free.

constexpr int BB = 8;
constexpr int NN = 2048;
constexpr int FF = 128;

constexpr int BM = 128, BN = 128, BK = 32;
constexpr int LDA_S = 36;                 // A smem stride (floats): bank = (4g+t)%32 -> conflict-free frags
constexpr int LDB_S = 136;                // B smem stride (floats): bank = (8t+g)%32 -> conflict-free frags
constexpr int A_TILE = BM * LDA_S;        // 4608 floats
constexpr int B_TILE = BK * LDB_S;        // 4352 floats
constexpr int STAGE  = A_TILE + B_TILE;   // 8960 floats per pipeline stage
constexpr int SMEM_BYTES = 2 * STAGE * 4; // 71680 B (double buffered)

// tf32 keeps the top 19 bits (1 sign + 8 exp + 10 mantissa)
constexpr unsigned TF32_MASK = 0xFFFFE000u;

// Scratch for support = x @ W  (8 MB, device global: no allocation)
__device__ float g_support[BB * NN * FF];

__device__ __forceinline__ void cp_async16(void* dst, const void* src) {
    unsigned d = (unsigned)__cvta_generic_to_shared(dst);
    asm volatile("cp.async.cg.shared.global [%0], [%1], 16;" :: "r"(d), "l"(src));
}
__device__ __forceinline__ void cp_commit() { asm volatile("cp.async.commit_group;"); }
__device__ __forceinline__ void cp_wait1()  { asm volatile("cp.async.wait_group 1;"); }
__device__ __forceinline__ void cp_wait0()  { asm volatile("cp.async.wait_group 0;"); }

// m16n8k8 TF32 MMA, fp32 accum. Raw fp32 bits fed as tf32 (HW truncates low mantissa).
__device__ __forceinline__ void mma_tf32(float c[4], const unsigned a[4],
                                         unsigned b0, unsigned b1) {
    asm volatile(
        "mma.sync.aligned.m16n8k8.row.col.f32.tf32.tf32.f32 "
        "{%0,%1,%2,%3}, {%4,%5,%6,%7}, {%8,%9}, {%0,%1,%2,%3};"
        : "+f"(c[0]), "+f"(c[1]), "+f"(c[2]), "+f"(c[3])
        : "r"(a[0]), "r"(a[1]), "r"(a[2]), "r"(a[3]), "r"(b0), "r"(b1));
}

// Exact low part of the tf32 split: v - trunc19(v). (Same exponent -> exact FADD.)
__device__ __forceinline__ unsigned tf32_lo(float v) {
    float hi = __uint_as_float(__float_as_uint(v) & TF32_MASK);
    return __float_as_uint(v - hi);
}

// Stage one (128x32 A, 32x128 B) fp32 tile pair into padded smem via cp.async.
__device__ __forceinline__ void stage_tiles(const float* __restrict__ Ag, int lda,
                                            const float* __restrict__ Bg,
                                            float* As, float* Bs, int tid) {
#pragma unroll
    for (int i = 0; i < 4; i++) {               // A: 128 rows x 32 cols = 1024 float4 / 256 thr
        int idx = tid + i * 256;
        int r = idx >> 3, c = idx & 7;          // 8 float4 per 128B row -> coalesced
        cp_async16(As + r * LDA_S + c * 4, Ag + (size_t)r * lda + c * 4);
    }
#pragma unroll
    for (int i = 0; i < 4; i++) {               // B: 32 rows x 128 cols
        int idx = tid + i * 256;
        int r = idx >> 5, c = idx & 31;
        cp_async16(Bs + r * LDB_S + c * 4, Bg + r * FF + c * 4);
    }
}

template<bool PHASE2>
__global__ __launch_bounds__(256, 1)
void gemm_tf32_kernel(const float* __restrict__ Aall,
                      const float* __restrict__ Bext,
                      const float* __restrict__ bias,
                      float* __restrict__ Cext,
                      int lda, int kchunks)
{
    extern __shared__ float smem[];
    float* AsBuf[2] = { smem,          smem + STAGE };
    float* BsBuf[2] = { smem + A_TILE, smem + STAGE + A_TILE };

    const int tid   = threadIdx.x;
    const int b     = blockIdx.y;
    const int mtile = blockIdx.x;

    const float* A  = Aall + (PHASE2 ? (size_t)b * NN * NN : 0) + (size_t)mtile * BM * lda;
    const float* Bm = PHASE2 ? (g_support + (size_t)b * NN * FF) : Bext;
    float* C = (PHASE2 ? (Cext + (size_t)b * NN * FF) : g_support) + (size_t)mtile * BM * FF;

    const int warp = tid >> 5;
    const int lane = tid & 31;
    const int wm = (warp & 1) * 64;   // 2 warps along M (64 rows each)
    const int wn = (warp >> 1) * 32;  // 4 warps along N (32 cols each)
    const int g  = lane >> 2;         // groupID
    const int t  = lane & 3;          // threadID_in_group

    float acc[4][4][4];
#pragma unroll
    for (int i = 0; i < 4; i++)
#pragma unroll
        for (int j = 0; j < 4; j++)
#pragma unroll
            for (int k = 0; k < 4; k++) acc[i][j][k] = 0.f;

    stage_tiles(A, lda, Bm, AsBuf[0], BsBuf[0], tid);
    cp_commit();

    for (int kc = 0; kc < kchunks; kc++) {
        if (kc + 1 < kchunks) {
            stage_tiles(A + (kc + 1) * BK, lda, Bm + (size_t)(kc + 1) * BK * FF,
                        AsBuf[(kc + 1) & 1], BsBuf[(kc + 1) & 1], tid);
            cp_commit();
            cp_wait1();
        } else {
            cp_wait0();
        }
        __syncthreads();

        const float* Asc = AsBuf[kc & 1];
        const float* Bsc = BsBuf[kc & 1];
#pragma unroll
        for (int ks = 0; ks < 4; ks++) {
            unsigned a[4][4], al[4][4];
            unsigned bb[4][2], bl[4][2];
            const float* Ab = Asc + (wm + g) * LDA_S + ks * 8 + t;
#pragma unroll
            for (int mf = 0; mf < 4; mf++) {
                float v0 = Ab[(mf * 16)     * LDA_S];
                float v1 = Ab[(mf * 16 + 8) * LDA_S];
                float v2 = Ab[(mf * 16)     * LDA_S + 4];
                float v3 = Ab[(mf * 16 + 8) * LDA_S + 4];
                a[mf][0] = __float_as_uint(v0);  al[mf][0] = tf32_lo(v0);
                a[mf][1] = __float_as_uint(v1);  al[mf][1] = tf32_lo(v1);
                a[mf][2] = __float_as_uint(v2);  al[mf][2] = tf32_lo(v2);
                a[mf][3] = __float_as_uint(v3);  al[mf][3] = tf32_lo(v3);
            }
            const float* Bb = Bsc + (ks * 8 + t) * LDB_S + wn + g;
#pragma unroll
            for (int nf = 0; nf < 4; nf++) {
                float w0 = Bb[nf * 8];
                float w1 = Bb[4 * LDB_S + nf * 8];
                bb[nf][0] = __float_as_uint(w0);  bl[nf][0] = tf32_lo(w0);
                bb[nf][1] = __float_as_uint(w1);  bl[nf][1] = tf32_lo(w1);
            }
#pragma unroll
            for (int mf = 0; mf < 4; mf++)
#pragma unroll
                for (int nf = 0; nf < 4; nf++) {
                    // correction terms first, main term last
                    mma_tf32(acc[mf][nf], al[mf], bb[nf][0], bb[nf][1]); // a_lo * b_hi
                    mma_tf32(acc[mf][nf], a[mf],  bl[nf][0], bl[nf][1]); // a_hi * b_lo (+ tiny)
                    mma_tf32(acc[mf][nf], a[mf],  bb[nf][0], bb[nf][1]); // a_hi * b_hi
                }
        }
        __syncthreads();
    }

    // Epilogue: c0/c1 are (row g, cols 2t,2t+1); c2/c3 same cols at row g+8 -> float2 stores.
#pragma unroll
    for (int mf = 0; mf < 4; mf++) {
        int r0 = wm + mf * 16 + g;
#pragma unroll
        for (int nf = 0; nf < 4; nf++) {
            int col = wn + nf * 8 + 2 * t;
            float2 v0 = make_float2(acc[mf][nf][0], acc[mf][nf][1]);
            float2 v1 = make_float2(acc[mf][nf][2], acc[mf][nf][3]);
            if (PHASE2) {
                float2 bz = *reinterpret_cast<const float2*>(bias + col);
                v0.x += bz.x; v0.y += bz.y;
                v1.x += bz.x; v1.y += bz.y;
            }
            *reinterpret_cast<float2*>(C + (size_t)r0       * FF + col) = v0;
            *reinterpret_cast<float2*>(C + (size_t)(r0 + 8) * FF + col) = v1;
        }
    }
}

extern "C" void kernel_launch(void* const* d_in, const int* in_sizes, int n_in,
                              void* d_out, int out_size) {
    const float* x    = (const float*)d_in[0];   // [8, 2048, 128]
    const float* adj  = (const float*)d_in[1];   // [8, 2048, 2048]
    const float* w    = (const float*)d_in[2];   // [128, 128]
    const float* bias = (const float*)d_in[3];   // [128]
    float* out = (float*)d_out;                  // [8, 2048, 128]

    cudaFuncSetAttribute(gemm_tf32_kernel<false>,
                         cudaFuncAttributeMaxDynamicSharedMemorySize, SMEM_BYTES);
    cudaFuncSetAttribute(gemm_tf32_kernel<true>,
                         cudaFuncAttributeMaxDynamicSharedMemorySize, SMEM_BYTES);

    // Phase 1: support = x @ W   (M=16384 folded over batch, K=128)
    gemm_tf32_kernel<false><<<dim3((BB * NN) / BM, 1), 256, SMEM_BYTES>>>(
        x, w, nullptr, nullptr, FF, FF / BK);

    // Phase 2: out[b] = adj[b] @ support[b] + bias   (K=2048)
    gemm_tf32_kernel<true><<<dim3(NN / BM, BB), 256, SMEM_BYTES>>>(
        adj, nullptr, bias, out, NN, NN / BK);
}

// round 4
// speedup vs baseline: 1.4704x; 1.4704x over previous
#include <cuda_runtime.h>
#include <cuda_bf16.h>
#include <cstdint>

// GraphConvolution: out[b] = adj[b] @ (x[b] @ W) + bias
// B=8, N=2048, F=128.
// Phase 1: legacy 3xTF32 mma.sync, writes support TRANSPOSED (supportT[b][f][n]).
// Phase 2: legacy 3xBF16 (error-compensated split) mma.sync m16n8k16,
//          512 threads, fp32 raw staged via cp.async then split to bf16 hi/lo in smem.

constexpr int BB = 8;
constexpr int NN = 2048;
constexpr int FF = 128;
constexpr unsigned TF32_MASK = 0xFFFFE000u;

// supportT[b][f][n] : K-major rows of length NN (8 MB scratch)
__device__ float g_supportT[BB * FF * NN];

// ---------------- common helpers ----------------
__device__ __forceinline__ unsigned s2u(const void* p) {
    return (unsigned)__cvta_generic_to_shared(p);
}
__device__ __forceinline__ void cp16(void* dst, const void* src) {
    asm volatile("cp.async.cg.shared.global [%0], [%1], 16;" :: "r"(s2u(dst)), "l"(src));
}
__device__ __forceinline__ void cpcommit() { asm volatile("cp.async.commit_group;"); }
__device__ __forceinline__ void cpwait1()  { asm volatile("cp.async.wait_group 1;"); }
__device__ __forceinline__ void cpwait0()  { asm volatile("cp.async.wait_group 0;"); }

// ======================================================================
// Phase 1: support = x @ W (legacy 3xTF32 mma.sync), transposed store
// ======================================================================
constexpr int P1_BM = 128, P1_BK = 32;
constexpr int LDA_S = 36;
constexpr int LDB_S = 136;
constexpr int A_TILE = P1_BM * LDA_S;
constexpr int B_TILE = P1_BK * LDB_S;
constexpr int STAGE1 = A_TILE + B_TILE;
constexpr int P1_SMEM = 2 * STAGE1 * 4;

__device__ __forceinline__ void mma_tf32_legacy(float c[4], const unsigned a[4],
                                                unsigned b0, unsigned b1) {
    asm volatile(
        "mma.sync.aligned.m16n8k8.row.col.f32.tf32.tf32.f32 "
        "{%0,%1,%2,%3}, {%4,%5,%6,%7}, {%8,%9}, {%0,%1,%2,%3};"
        : "+f"(c[0]), "+f"(c[1]), "+f"(c[2]), "+f"(c[3])
        : "r"(a[0]), "r"(a[1]), "r"(a[2]), "r"(a[3]), "r"(b0), "r"(b1));
}
__device__ __forceinline__ unsigned tf32_lo_bits(float v) {
    float hi = __uint_as_float(__float_as_uint(v) & TF32_MASK);
    return __float_as_uint(v - hi);
}

__global__ __launch_bounds__(256, 1)
void phase1_kernel(const float* __restrict__ x, const float* __restrict__ w)
{
    extern __shared__ float smem1[];
    float* AsBuf[2] = { smem1,          smem1 + STAGE1 };
    float* BsBuf[2] = { smem1 + A_TILE, smem1 + STAGE1 + A_TILE };

    const int tid = threadIdx.x;
    const int mtile = blockIdx.x;            // 128 tiles over 16384 rows
    const float* A = x + (size_t)mtile * P1_BM * FF;

    const int warp = tid >> 5, lane = tid & 31;
    const int wm = (warp & 1) * 64;
    const int wn = (warp >> 1) * 32;
    const int g = lane >> 2, t = lane & 3;

    float acc[4][4][4];
#pragma unroll
    for (int i = 0; i < 4; i++)
#pragma unroll
        for (int j = 0; j < 4; j++)
#pragma unroll
            for (int k = 0; k < 4; k++) acc[i][j][k] = 0.f;

    auto stage = [&](int kc, int buf) {
#pragma unroll
        for (int i = 0; i < 4; i++) {
            int idx = tid + i * 256;
            int r = idx >> 3, c = idx & 7;
            cp16(AsBuf[buf] + r * LDA_S + c * 4, A + (size_t)r * FF + kc * P1_BK + c * 4);
        }
#pragma unroll
        for (int i = 0; i < 4; i++) {
            int idx = tid + i * 256;
            int r = idx >> 5, c = idx & 31;
            cp16(BsBuf[buf] + r * LDB_S + c * 4, w + (size_t)(kc * P1_BK + r) * FF + c * 4);
        }
        cpcommit();
    };
    stage(0, 0);

    for (int kc = 0; kc < 4; kc++) {
        if (kc + 1 < 4) { stage(kc + 1, (kc + 1) & 1); cpwait1(); }
        else            { cpwait0(); }
        __syncthreads();
        const float* Asc = AsBuf[kc & 1];
        const float* Bsc = BsBuf[kc & 1];
#pragma unroll
        for (int ks = 0; ks < 4; ks++) {
            unsigned a[4][4], al[4][4], bb[4][2], bl[4][2];
            const float* Ab = Asc + (wm + g) * LDA_S + ks * 8 + t;
#pragma unroll
            for (int mf = 0; mf < 4; mf++) {
                float v0 = Ab[(mf * 16) * LDA_S];
                float v1 = Ab[(mf * 16 + 8) * LDA_S];
                float v2 = Ab[(mf * 16) * LDA_S + 4];
                float v3 = Ab[(mf * 16 + 8) * LDA_S + 4];
                a[mf][0] = __float_as_uint(v0); al[mf][0] = tf32_lo_bits(v0);
                a[mf][1] = __float_as_uint(v1); al[mf][1] = tf32_lo_bits(v1);
                a[mf][2] = __float_as_uint(v2); al[mf][2] = tf32_lo_bits(v2);
                a[mf][3] = __float_as_uint(v3); al[mf][3] = tf32_lo_bits(v3);
            }
            const float* Bb = Bsc + (ks * 8 + t) * LDB_S + wn + g;
#pragma unroll
            for (int nf = 0; nf < 4; nf++) {
                float w0 = Bb[nf * 8];
                float w1 = Bb[4 * LDB_S + nf * 8];
                bb[nf][0] = __float_as_uint(w0); bl[nf][0] = tf32_lo_bits(w0);
                bb[nf][1] = __float_as_uint(w1); bl[nf][1] = tf32_lo_bits(w1);
            }
#pragma unroll
            for (int mf = 0; mf < 4; mf++)
#pragma unroll
                for (int nf = 0; nf < 4; nf++) {
                    mma_tf32_legacy(acc[mf][nf], al[mf], bb[nf][0], bb[nf][1]);
                    mma_tf32_legacy(acc[mf][nf], a[mf],  bl[nf][0], bl[nf][1]);
                    mma_tf32_legacy(acc[mf][nf], a[mf],  bb[nf][0], bb[nf][1]);
                }
        }
        __syncthreads();
    }

    // transposed store: supportT[b][col][n]
    const int b = mtile >> 4;
    const int nbase = (mtile & 15) * P1_BM;
    float* base = g_supportT + (size_t)b * FF * NN;
#pragma unroll
    for (int mf = 0; mf < 4; mf++) {
        int nl = nbase + wm + mf * 16 + g;
#pragma unroll
        for (int nf = 0; nf < 4; nf++) {
            int col = wn + nf * 8 + 2 * t;
            base[(size_t)col * NN + nl]           = acc[mf][nf][0];
            base[(size_t)(col + 1) * NN + nl]     = acc[mf][nf][1];
            base[(size_t)col * NN + nl + 8]       = acc[mf][nf][2];
            base[(size_t)(col + 1) * NN + nl + 8] = acc[mf][nf][3];
        }
    }
}

// ======================================================================
// Phase 2: out[b] = adj[b] @ support[b] + bias   (3xBF16 mma.sync m16n8k16)
// ======================================================================
// SMEM: bias 512B | raw fp32 2x(A 16K + B 16K) | bf16 2x(Ahi,Alo,Bhi,Blo @ 10240B)
constexpr int RAW_STG   = 32768;            // per stage raw bytes (A then B)
constexpr int OFF_BIAS  = 0;
constexpr int OFF_RAW   = 1024;
constexpr int OFF_BF16  = OFF_RAW + 2 * RAW_STG;       // 66560
constexpr int LDH       = 40;               // halves per row in bf16 tiles (padded)
constexpr int HT_BYTES  = 128 * LDH * 2;    // 10240 per tile
constexpr int BF_STG    = 4 * HT_BYTES;     // 40960 per buffer
constexpr int P2_SMEM   = OFF_BF16 + 2 * BF_STG;       // 148480

__device__ __forceinline__ void mma_bf16(float c[4], unsigned a0, unsigned a1,
                                         unsigned a2, unsigned a3,
                                         unsigned b0, unsigned b1) {
    asm volatile(
        "mma.sync.aligned.m16n8k16.row.col.f32.bf16.bf16.f32 "
        "{%0,%1,%2,%3}, {%4,%5,%6,%7}, {%8,%9}, {%0,%1,%2,%3};"
        : "+f"(c[0]), "+f"(c[1]), "+f"(c[2]), "+f"(c[3])
        : "r"(a0), "r"(a1), "r"(a2), "r"(a3), "r"(b0), "r"(b1));
}

// split fp32 pair -> bf16x2 hi (exact-ish) + bf16x2 lo (residual)
__device__ __forceinline__ void split2(float x, float y, unsigned& h, unsigned& l) {
    __nv_bfloat162 hh = __float22bfloat162_rn(make_float2(x, y));   // .x low half
    unsigned hb = *reinterpret_cast<unsigned*>(&hh);
    float lx = x - __uint_as_float(hb << 16);
    float ly = y - __uint_as_float(hb & 0xFFFF0000u);
    __nv_bfloat162 ll = __float22bfloat162_rn(make_float2(lx, ly));
    h = hb;
    l = *reinterpret_cast<unsigned*>(&ll);
}

__global__ __launch_bounds__(512, 1)
void phase2_kernel(const float* __restrict__ adj, const float* __restrict__ bias,
                   float* __restrict__ out)
{
    extern __shared__ __align__(16) char smem[];
    const int tid = threadIdx.x, warp = tid >> 5, lane = tid & 31;
    const int mtile = blockIdx.x, b = blockIdx.y;

    const float* A  = adj + ((size_t)b * NN + (size_t)mtile * 128) * NN;
    const float* Bm = g_supportT + (size_t)b * FF * NN;
    float* C = out + ((size_t)b * NN + (size_t)mtile * 128) * FF;

    if (tid < 128) ((float*)(smem + OFF_BIAS))[tid] = bias[tid];

    const int g = lane >> 2, t = lane & 3;
    const int wm = (warp & 3) * 32;      // 4 warps along M
    const int wn = (warp >> 2) * 32;     // 4 warps along N

    float acc[2][4][4];
#pragma unroll
    for (int i = 0; i < 2; i++)
#pragma unroll
        for (int j = 0; j < 4; j++)
#pragma unroll
            for (int k = 0; k < 4; k++) acc[i][j][k] = 0.f;

    auto stage = [&](int kc) {
        char* ra = smem + OFF_RAW + (kc & 1) * RAW_STG;
#pragma unroll
        for (int i = 0; i < 2; i++) {
            int f4 = tid + i * 512;
            int r = f4 >> 3, c = f4 & 7;
            cp16(ra + r * 128 + c * 16,         A  + (size_t)r * NN + kc * 32 + c * 4);
            cp16(ra + 16384 + r * 128 + c * 16, Bm + (size_t)r * NN + kc * 32 + c * 4);
        }
        cpcommit();
    };

    auto convert = [&](int kc) {
        const char* ra = smem + OFF_RAW + (kc & 1) * RAW_STG;
        char* hb = smem + OFF_BF16 + (kc & 1) * BF_STG;
#pragma unroll
        for (int i = 0; i < 2; i++) {
            int f4 = tid + i * 512;
            int r = f4 >> 3, c4 = f4 & 7;
            int dsto = r * (LDH * 2) + c4 * 8;           // bytes into hi/lo tiles
            {   // A
                float4 v = *(const float4*)(ra + r * 128 + c4 * 16);
                uint2 h, l;
                split2(v.x, v.y, h.x, l.x);
                split2(v.z, v.w, h.y, l.y);
                *(uint2*)(hb + dsto)            = h;     // A_hi
                *(uint2*)(hb + HT_BYTES + dsto) = l;     // A_lo
            }
            {   // B
                float4 v = *(const float4*)(ra + 16384 + r * 128 + c4 * 16);
                uint2 h, l;
                split2(v.x, v.y, h.x, l.x);
                split2(v.z, v.w, h.y, l.y);
                *(uint2*)(hb + 2 * HT_BYTES + dsto) = h; // B_hi
                *(uint2*)(hb + 3 * HT_BYTES + dsto) = l; // B_lo
            }
        }
    };

    auto mma_chunk = [&](int s) {
        const char* hb = smem + OFF_BF16 + s * BF_STG;
        const char* Ahi = hb;
        const char* Alo = hb + HT_BYTES;
        const char* Bhi = hb + 2 * HT_BYTES;
        const char* Blo = hb + 3 * HT_BYTES;
#pragma unroll
        for (int ks = 0; ks < 2; ks++) {
            const int ko = ks * 32 + t * 4;              // byte offset of k-frag base
            unsigned ah[2][4], al[2][4], bh[4][2], bl[4][2];
#pragma unroll
            for (int mf = 0; mf < 2; mf++) {
                int ro = (wm + mf * 16 + g) * (LDH * 2) + ko;
                ah[mf][0] = *(const unsigned*)(Ahi + ro);
                ah[mf][1] = *(const unsigned*)(Ahi + ro + 8 * LDH * 2);
                ah[mf][2] = *(const unsigned*)(Ahi + ro + 16);
                ah[mf][3] = *(const unsigned*)(Ahi + ro + 8 * LDH * 2 + 16);
                al[mf][0] = *(const unsigned*)(Alo + ro);
                al[mf][1] = *(const unsigned*)(Alo + ro + 8 * LDH * 2);
                al[mf][2] = *(const unsigned*)(Alo + ro + 16);
                al[mf][3] = *(const unsigned*)(Alo + ro + 8 * LDH * 2 + 16);
            }
#pragma unroll
            for (int nf = 0; nf < 4; nf++) {
                int ro = (wn + nf * 8 + g) * (LDH * 2) + ko;
                bh[nf][0] = *(const unsigned*)(Bhi + ro);
                bh[nf][1] = *(const unsigned*)(Bhi + ro + 16);
                bl[nf][0] = *(const unsigned*)(Blo + ro);
                bl[nf][1] = *(const unsigned*)(Blo + ro + 16);
            }
#pragma unroll
            for (int mf = 0; mf < 2; mf++)
#pragma unroll
                for (int nf = 0; nf < 4; nf++) {
                    mma_bf16(acc[mf][nf], al[mf][0], al[mf][1], al[mf][2], al[mf][3],
                             bh[nf][0], bh[nf][1]);
                    mma_bf16(acc[mf][nf], ah[mf][0], ah[mf][1], ah[mf][2], ah[mf][3],
                             bl[nf][0], bl[nf][1]);
                    mma_bf16(acc[mf][nf], ah[mf][0], ah[mf][1], ah[mf][2], ah[mf][3],
                             bh[nf][0], bh[nf][1]);
                }
        }
    };

    // prologue
    stage(0);
    stage(1);
    cpwait1();
    __syncthreads();
    convert(0);
    __syncthreads();

    for (int kc = 0; kc < 64; kc++) {
        mma_chunk(kc & 1);
        if (kc + 1 < 64) {
            cpwait0();
            __syncthreads();
            convert(kc + 1);
            if (kc + 2 < 64) stage(kc + 2);
            __syncthreads();
        }
    }

    // epilogue
    const float* bs = (const float*)(smem + OFF_BIAS);
#pragma unroll
    for (int mf = 0; mf < 2; mf++) {
        int r0 = wm + mf * 16 + g;
#pragma unroll
        for (int nf = 0; nf < 4; nf++) {
            int col = wn + nf * 8 + 2 * t;
            float2 bz = *reinterpret_cast<const float2*>(bs + col);
            float2 v0 = make_float2(acc[mf][nf][0] + bz.x, acc[mf][nf][1] + bz.y);
            float2 v1 = make_float2(acc[mf][nf][2] + bz.x, acc[mf][nf][3] + bz.y);
            *reinterpret_cast<float2*>(C + (size_t)r0       * FF + col) = v0;
            *reinterpret_cast<float2*>(C + (size_t)(r0 + 8) * FF + col) = v1;
        }
    }
}

// ======================================================================
extern "C" void kernel_launch(void* const* d_in, const int* in_sizes, int n_in,
                              void* d_out, int out_size) {
    const float* x    = (const float*)d_in[0];   // [8, 2048, 128]
    const float* adj  = (const float*)d_in[1];   // [8, 2048, 2048]
    const float* w    = (const float*)d_in[2];   // [128, 128]
    const float* bias = (const float*)d_in[3];   // [128]
    float* out = (float*)d_out;                  // [8, 2048, 128]

    cudaFuncSetAttribute(phase1_kernel, cudaFuncAttributeMaxDynamicSharedMemorySize, P1_SMEM);
    cudaFuncSetAttribute(phase2_kernel, cudaFuncAttributeMaxDynamicSharedMemorySize, P2_SMEM);

    phase1_kernel<<<(BB * NN) / P1_BM, 256, P1_SMEM>>>(x, w);
    phase2_kernel<<<dim3(NN / 128, BB), 512, P2_SMEM>>>(adj, bias, out);
}

// round 5
// speedup vs baseline: 2.1497x; 1.4620x over previous
#include <cuda_runtime.h>
#include <cuda_fp16.h>
#include <cstdint>

// GraphConvolution: out[b] = adj[b] @ (x[b] @ W) + bias
// B=8, N=2048, F=128.
// Phase 1: legacy 3xTF32 mma.sync (fp32-accurate support), emits support as
//          f16 hi/lo planes, layout [b*N + n][f] (k-major for phase-2 B).
// Phase 2: 2-term FP16 mma.sync m16n8k16:  out = a_f16 * (b_hi + b_lo)
//          adj converted on the fly (LDG->cvt->STS), support staged via cp.async,
//          ldmatrix fragments, triple-buffered, 1 syncthreads per k-chunk.

constexpr int BB = 8;
constexpr int NN = 2048;
constexpr int FF = 128;
constexpr unsigned TF32_MASK = 0xFFFFE000u;

// support planes: [BB*NN][FF] f16 (4 MB each)
__device__ __half g_sup_hi[BB * NN * FF];
__device__ __half g_sup_lo[BB * NN * FF];

// ---------------- common helpers ----------------
__device__ __forceinline__ unsigned s2u(const void* p) {
    return (unsigned)__cvta_generic_to_shared(p);
}
__device__ __forceinline__ void cp16(void* dst, const void* src) {
    asm volatile("cp.async.cg.shared.global [%0], [%1], 16;" :: "r"(s2u(dst)), "l"(src));
}
__device__ __forceinline__ void cpcommit() { asm volatile("cp.async.commit_group;"); }
__device__ __forceinline__ void cpwait1()  { asm volatile("cp.async.wait_group 1;"); }
__device__ __forceinline__ void cpwait0()  { asm volatile("cp.async.wait_group 0;"); }

__device__ __forceinline__ void ldsm_x4(unsigned r[4], unsigned a) {
    asm volatile("ldmatrix.sync.aligned.m8n8.x4.shared.b16 {%0,%1,%2,%3}, [%4];"
                 : "=r"(r[0]), "=r"(r[1]), "=r"(r[2]), "=r"(r[3]) : "r"(a));
}
__device__ __forceinline__ void ldsm_x4_t(unsigned r[4], unsigned a) {
    asm volatile("ldmatrix.sync.aligned.m8n8.x4.trans.shared.b16 {%0,%1,%2,%3}, [%4];"
                 : "=r"(r[0]), "=r"(r[1]), "=r"(r[2]), "=r"(r[3]) : "r"(a));
}
__device__ __forceinline__ void mma_f16(float c[4], const unsigned a[4],
                                        unsigned b0, unsigned b1) {
    asm volatile(
        "mma.sync.aligned.m16n8k16.row.col.f32.f16.f16.f32 "
        "{%0,%1,%2,%3}, {%4,%5,%6,%7}, {%8,%9}, {%0,%1,%2,%3};"
        : "+f"(c[0]), "+f"(c[1]), "+f"(c[2]), "+f"(c[3])
        : "r"(a[0]), "r"(a[1]), "r"(a[2]), "r"(a[3]), "r"(b0), "r"(b1));
}

// ======================================================================
// Phase 1: support = x @ W (legacy 3xTF32), stores f16 hi/lo planes
// ======================================================================
constexpr int P1_BM = 128, P1_BK = 32;
constexpr int LDA_S = 36;
constexpr int LDB_S = 136;
constexpr int A_TILE1 = P1_BM * LDA_S;
constexpr int B_TILE1 = P1_BK * LDB_S;
constexpr int STAGE1 = A_TILE1 + B_TILE1;
constexpr int P1_SMEM = 2 * STAGE1 * 4;

__device__ __forceinline__ void mma_tf32_legacy(float c[4], const unsigned a[4],
                                                unsigned b0, unsigned b1) {
    asm volatile(
        "mma.sync.aligned.m16n8k8.row.col.f32.tf32.tf32.f32 "
        "{%0,%1,%2,%3}, {%4,%5,%6,%7}, {%8,%9}, {%0,%1,%2,%3};"
        : "+f"(c[0]), "+f"(c[1]), "+f"(c[2]), "+f"(c[3])
        : "r"(a[0]), "r"(a[1]), "r"(a[2]), "r"(a[3]), "r"(b0), "r"(b1));
}
__device__ __forceinline__ unsigned tf32_lo_bits(float v) {
    float hi = __uint_as_float(__float_as_uint(v) & TF32_MASK);
    return __float_as_uint(v - hi);
}
// split (x,y) -> f16 hi pair + f16 lo (residual) pair
__device__ __forceinline__ void split_h2(float x, float y, __half2& h, __half2& l) {
    h = __floats2half2_rn(x, y);
    float lx = x - __half2float(__low2half(h));
    float ly = y - __half2float(__high2half(h));
    l = __floats2half2_rn(lx, ly);
}

__global__ __launch_bounds__(256, 1)
void phase1_kernel(const float* __restrict__ x, const float* __restrict__ w)
{
    extern __shared__ float smem1[];
    float* AsBuf[2] = { smem1,           smem1 + STAGE1 };
    float* BsBuf[2] = { smem1 + A_TILE1, smem1 + STAGE1 + A_TILE1 };

    const int tid = threadIdx.x;
    const int mtile = blockIdx.x;            // 128 tiles over 16384 rows
    const float* A = x + (size_t)mtile * P1_BM * FF;

    const int warp = tid >> 5, lane = tid & 31;
    const int wm = (warp & 1) * 64;
    const int wn = (warp >> 1) * 32;
    const int g = lane >> 2, t = lane & 3;

    float acc[4][4][4];
#pragma unroll
    for (int i = 0; i < 4; i++)
#pragma unroll
        for (int j = 0; j < 4; j++)
#pragma unroll
            for (int k = 0; k < 4; k++) acc[i][j][k] = 0.f;

    auto stage = [&](int kc, int buf) {
#pragma unroll
        for (int i = 0; i < 4; i++) {
            int idx = tid + i * 256;
            int r = idx >> 3, c = idx & 7;
            cp16(AsBuf[buf] + r * LDA_S + c * 4, A + (size_t)r * FF + kc * P1_BK + c * 4);
        }
#pragma unroll
        for (int i = 0; i < 4; i++) {
            int idx = tid + i * 256;
            int r = idx >> 5, c = idx & 31;
            cp16(BsBuf[buf] + r * LDB_S + c * 4, w + (size_t)(kc * P1_BK + r) * FF + c * 4);
        }
        cpcommit();
    };
    stage(0, 0);

    for (int kc = 0; kc < 4; kc++) {
        if (kc + 1 < 4) { stage(kc + 1, (kc + 1) & 1); cpwait1(); }
        else            { cpwait0(); }
        __syncthreads();
        const float* Asc = AsBuf[kc & 1];
        const float* Bsc = BsBuf[kc & 1];
#pragma unroll
        for (int ks = 0; ks < 4; ks++) {
            unsigned a[4][4], al[4][4], bb[4][2], bl[4][2];
            const float* Ab = Asc + (wm + g) * LDA_S + ks * 8 + t;
#pragma unroll
            for (int mf = 0; mf < 4; mf++) {
                float v0 = Ab[(mf * 16) * LDA_S];
                float v1 = Ab[(mf * 16 + 8) * LDA_S];
                float v2 = Ab[(mf * 16) * LDA_S + 4];
                float v3 = Ab[(mf * 16 + 8) * LDA_S + 4];
                a[mf][0] = __float_as_uint(v0); al[mf][0] = tf32_lo_bits(v0);
                a[mf][1] = __float_as_uint(v1); al[mf][1] = tf32_lo_bits(v1);
                a[mf][2] = __float_as_uint(v2); al[mf][2] = tf32_lo_bits(v2);
                a[mf][3] = __float_as_uint(v3); al[mf][3] = tf32_lo_bits(v3);
            }
            const float* Bb = Bsc + (ks * 8 + t) * LDB_S + wn + g;
#pragma unroll
            for (int nf = 0; nf < 4; nf++) {
                float w0 = Bb[nf * 8];
                float w1 = Bb[4 * LDB_S + nf * 8];
                bb[nf][0] = __float_as_uint(w0); bl[nf][0] = tf32_lo_bits(w0);
                bb[nf][1] = __float_as_uint(w1); bl[nf][1] = tf32_lo_bits(w1);
            }
#pragma unroll
            for (int mf = 0; mf < 4; mf++)
#pragma unroll
                for (int nf = 0; nf < 4; nf++) {
                    mma_tf32_legacy(acc[mf][nf], al[mf], bb[nf][0], bb[nf][1]);
                    mma_tf32_legacy(acc[mf][nf], a[mf],  bl[nf][0], bl[nf][1]);
                    mma_tf32_legacy(acc[mf][nf], a[mf],  bb[nf][0], bb[nf][1]);
                }
        }
        __syncthreads();
    }

    // store hi/lo f16 planes, non-transposed: [row][f]
    const int rowbase = mtile * P1_BM;
#pragma unroll
    for (int mf = 0; mf < 4; mf++) {
        int r0 = rowbase + wm + mf * 16 + g;
#pragma unroll
        for (int nf = 0; nf < 4; nf++) {
            int col = wn + nf * 8 + 2 * t;
            __half2 h, l;
            split_h2(acc[mf][nf][0], acc[mf][nf][1], h, l);
            *(__half2*)(g_sup_hi + (size_t)r0 * FF + col) = h;
            *(__half2*)(g_sup_lo + (size_t)r0 * FF + col) = l;
            split_h2(acc[mf][nf][2], acc[mf][nf][3], h, l);
            *(__half2*)(g_sup_hi + (size_t)(r0 + 8) * FF + col) = h;
            *(__half2*)(g_sup_lo + (size_t)(r0 + 8) * FF + col) = l;
        }
    }
}

// ======================================================================
// Phase 2: out[b] = adj[b] @ support[b] + bias   (2xFP16 mma m16n8k16)
// ======================================================================
// smem: bias 512B | A f16 3x(128 rows x 40 halves = 10240B) | B 3x(hi+lo planes)
constexpr int LDA_H    = 40;                 // halves per A row (32 + 8 pad)
constexpr int A_TILE_B = 128 * LDA_H * 2;    // 10240
constexpr int LDB_B    = 272;                // bytes per B row (256 + 16 pad)
constexpr int B_PLANE  = 32 * LDB_B;         // 8704
constexpr int B_STG_B  = 2 * B_PLANE;        // 17408 (hi, lo)
constexpr int OFF_BIAS = 0;
constexpr int OFF_A    = 1024;
constexpr int OFF_B    = OFF_A + 3 * A_TILE_B;        // 31744
constexpr int P2_SMEM  = OFF_B + 3 * B_STG_B;         // 83968

__global__ __launch_bounds__(512, 1)
void phase2_kernel(const float* __restrict__ adj, const float* __restrict__ bias,
                   float* __restrict__ out)
{
    extern __shared__ __align__(16) char smem[];
    const unsigned sA = s2u(smem + OFF_A);
    const unsigned sB = s2u(smem + OFF_B);
    const int tid = threadIdx.x, warp = tid >> 5, lane = tid & 31;
    const int mtile = blockIdx.x, b = blockIdx.y;

    const float* A = adj + ((size_t)b * NN + (size_t)mtile * 128) * NN;
    const __half* BH = g_sup_hi + (size_t)b * NN * FF;
    const __half* BL = g_sup_lo + (size_t)b * NN * FF;
    float* C = out + ((size_t)b * NN + (size_t)mtile * 128) * FF;

    if (tid < 128) ((float*)(smem + OFF_BIAS))[tid] = bias[tid];

    // staging roles
    const int ar = tid >> 2, aq = tid & 3;        // A: row, 8-float quarter
    const int br = tid >> 4, bs = tid & 15;       // B: row (32), 16B segment

    // fragment geometry
    const int g = lane >> 2, t = lane & 3;
    const int wm = (warp & 3) * 32;               // M within 128
    const int wn = (warp >> 2) * 32;              // N(f) within 128
    // ldmatrix lane offsets
    const unsigned aoff = (unsigned)((wm + (lane & 7) + ((lane >> 3) & 1) * 8) * (LDA_H * 2)
                                     + ((lane >> 4) * 8) * 2);
    const unsigned boff = (unsigned)(((lane & 7) + ((lane >> 3) & 1) * 8) * LDB_B
                                     + (wn + (lane >> 4) * 8) * 2);

    float acc[2][4][4];
#pragma unroll
    for (int i = 0; i < 2; i++)
#pragma unroll
        for (int j = 0; j < 4; j++)
#pragma unroll
            for (int k = 0; k < 4; k++) acc[i][j][k] = 0.f;

    auto ldgA = [&](int kc, float4& v0, float4& v1) {
        const float* p = A + (size_t)ar * NN + kc * 32 + aq * 8;
        v0 = *(const float4*)p;
        v1 = *(const float4*)(p + 4);
    };
    auto stsA = [&](int kc, float4 v0, float4 v1) {
        __half2 p0 = __floats2half2_rn(v0.x, v0.y);
        __half2 p1 = __floats2half2_rn(v0.z, v0.w);
        __half2 p2 = __floats2half2_rn(v1.x, v1.y);
        __half2 p3 = __floats2half2_rn(v1.z, v1.w);
        uint4 u;
        u.x = *(unsigned*)&p0; u.y = *(unsigned*)&p1;
        u.z = *(unsigned*)&p2; u.w = *(unsigned*)&p3;
        *(uint4*)(smem + OFF_A + (kc % 3) * A_TILE_B + ar * (LDA_H * 2) + aq * 16) = u;
    };
    auto cpB = [&](int kc) {
        char* dst = smem + OFF_B + (kc % 3) * B_STG_B + br * LDB_B + bs * 16;
        const __half* sh = BH + (size_t)(kc * 32 + br) * FF + bs * 8;
        const __half* sl = BL + (size_t)(kc * 32 + br) * FF + bs * 8;
        cp16(dst, sh);
        cp16(dst + B_PLANE, sl);
        cpcommit();
    };

    auto mma_chunk = [&](int j) {
        const unsigned aB = sA + j * A_TILE_B;
        const unsigned bB = sB + j * B_STG_B;
#pragma unroll
        for (int ks = 0; ks < 2; ks++) {
            unsigned af[2][4];
            ldsm_x4(af[0], aB + aoff + ks * 32);
            ldsm_x4(af[1], aB + aoff + 16 * (LDA_H * 2) + ks * 32);
            unsigned bh[2][4], bl[2][4];
            const unsigned bks = bB + boff + ks * 16 * LDB_B;
            ldsm_x4_t(bh[0], bks);
            ldsm_x4_t(bh[1], bks + 32);
            ldsm_x4_t(bl[0], bks + B_PLANE);
            ldsm_x4_t(bl[1], bks + B_PLANE + 32);
#pragma unroll
            for (int mf = 0; mf < 2; mf++)
#pragma unroll
                for (int np = 0; np < 2; np++)
#pragma unroll
                    for (int p = 0; p < 2; p++) {
                        float* c = acc[mf][np * 2 + p];
                        mma_f16(c, af[mf], bl[np][p * 2], bl[np][p * 2 + 1]);
                        mma_f16(c, af[mf], bh[np][p * 2], bh[np][p * 2 + 1]);
                    }
        }
    };

    // prologue: chunks 0 and 1
    {
        float4 v0, v1;
        ldgA(0, v0, v1); stsA(0, v0, v1); cpB(0);
        ldgA(1, v0, v1); stsA(1, v0, v1); cpB(1);
    }

    for (int kc = 0; kc < 64; kc++) {
        float4 v0, v1;
        const bool pre = (kc + 2 < 64);
        if (pre) ldgA(kc + 2, v0, v1);           // overlap LDG with MMA below
        if (kc < 63) cpwait1(); else cpwait0();
        __syncthreads();
        mma_chunk(kc % 3);
        if (pre) {
            stsA(kc + 2, v0, v1);
            cpB(kc + 2);
        }
    }

    // epilogue
    const float* bsm = (const float*)(smem + OFF_BIAS);
#pragma unroll
    for (int mf = 0; mf < 2; mf++) {
        int r0 = wm + mf * 16 + g;
#pragma unroll
        for (int nf = 0; nf < 4; nf++) {
            int col = wn + nf * 8 + 2 * t;
            float2 bz = *reinterpret_cast<const float2*>(bsm + col);
            float2 u0 = make_float2(acc[mf][nf][0] + bz.x, acc[mf][nf][1] + bz.y);
            float2 u1 = make_float2(acc[mf][nf][2] + bz.x, acc[mf][nf][3] + bz.y);
            *reinterpret_cast<float2*>(C + (size_t)r0       * FF + col) = u0;
            *reinterpret_cast<float2*>(C + (size_t)(r0 + 8) * FF + col) = u1;
        }
    }
}

// ======================================================================
extern "C" void kernel_launch(void* const* d_in, const int* in_sizes, int n_in,
                              void* d_out, int out_size) {
    const float* x    = (const float*)d_in[0];   // [8, 2048, 128]
    const float* adj  = (const float*)d_in[1];   // [8, 2048, 2048]
    const float* w    = (const float*)d_in[2];   // [128, 128]
    const float* bias = (const float*)d_in[3];   // [128]
    float* out = (float*)d_out;                  // [8, 2048, 128]

    cudaFuncSetAttribute(phase1_kernel, cudaFuncAttributeMaxDynamicSharedMemorySize, P1_SMEM);
    cudaFuncSetAttribute(phase2_kernel, cudaFuncAttributeMaxDynamicSharedMemorySize, P2_SMEM);

    phase1_kernel<<<(BB * NN) / P1_BM, 256, P1_SMEM>>>(x, w);
    phase2_kernel<<<dim3(NN / 128, BB), 512, P2_SMEM>>>(adj, bias, out);
}